// round 4
// baseline (speedup 1.0000x reference)
#include <cuda_runtime.h>
#include <cuda_bf16.h>
#include <cstdint>

#define NN   50000
#define ECNT 800000

// ===================== helpers =============================================
__device__ __forceinline__ uint32_t smem_to_u32(const void* p) {
    uint32_t a;
    asm("{ .reg .u64 t; cvta.to.shared.u64 t, %1; cvt.u32.u64 %0, t; }"
        : "=r"(a) : "l"(p));
    return a;
}
__device__ __forceinline__ void ldsm_x4(uint32_t* r, uint32_t addr) {
    asm volatile("ldmatrix.sync.aligned.m8n8.x4.shared.b16 {%0,%1,%2,%3}, [%4];"
        : "=r"(r[0]), "=r"(r[1]), "=r"(r[2]), "=r"(r[3]) : "r"(addr));
}
__device__ __forceinline__ void mma_bf16(float* c, const uint32_t* a,
                                         uint32_t b0, uint32_t b1) {
    asm volatile("mma.sync.aligned.m16n8k16.row.col.f32.bf16.bf16.f32 "
        "{%0,%1,%2,%3}, {%4,%5,%6,%7}, {%8,%9}, {%0,%1,%2,%3};"
        : "+f"(c[0]), "+f"(c[1]), "+f"(c[2]), "+f"(c[3])
        : "r"(a[0]), "r"(a[1]), "r"(a[2]), "r"(a[3]), "r"(b0), "r"(b1));
}

// ---------------- scratch (device globals; no allocation allowed) ----------
__device__ float g_deg [NN];
__device__ float g_dinv[NN];
__device__ float g_aggx[(size_t)NN * 128];
__device__ float g_h1r [(size_t)NN * 256];
__device__ float g_h2  [(size_t)NN * 64];
__device__ float g_z   [(size_t)NN * 64];
__device__ float g_d   [(size_t)NN * 256];

// ---------------- degree / normalization ----------------------------------
__global__ void k_deg_init() {
    int i = blockIdx.x * 256 + threadIdx.x;
    if (i < NN) g_deg[i] = 1.0f;
}
__global__ void k_deg_count(const int* __restrict__ dst) {
    int e = blockIdx.x * 256 + threadIdx.x;
    if (e < ECNT) atomicAdd(&g_deg[dst[e]], 1.0f);
}
__global__ void k_dinv() {
    int i = blockIdx.x * 256 + threadIdx.x;
    if (i < NN) g_dinv[i] = rsqrtf(g_deg[i]);
}

// ============ bf16x3 tensor-core GEMM: C = A[MxK]@B[KxN] (+bias)(relu) =====
// CTA tile 128x64, 8 warps (4m x 2n), warp tile 32x32 = 2x4 m16n8k16 tiles.
// A,B split hi/lo bf16; acc += Ah*Bh + Ah*Bl + Al*Bh (fp32).
template<int KTOT, bool BIAS, bool RELU>
__global__ void __launch_bounds__(256, 2)
k_gemm_mma(const float* __restrict__ A, const float* __restrict__ Bw,
           const float* __restrict__ bias, float* __restrict__ C, int NTOT)
{
    constexpr int M  = NN;
    constexpr int TK = 64;
    constexpr int ST = TK + 8;             // 72 bf16 = 144B row stride
    constexpr int NSTAGE = KTOT / TK;
    constexpr int A_SZ = 128 * ST * 2;     // 18432 B
    constexpr int B_SZ = 64 * ST * 2;      //  9216 B

    extern __shared__ char smem[];
    __nv_bfloat16* AH = (__nv_bfloat16*)(smem);
    __nv_bfloat16* AL = (__nv_bfloat16*)(smem + A_SZ);
    __nv_bfloat16* BH = (__nv_bfloat16*)(smem + 2 * A_SZ);
    __nv_bfloat16* BL = (__nv_bfloat16*)(smem + 2 * A_SZ + B_SZ);

    int tid = threadIdx.x, l = tid & 31, wid = tid >> 5;
    int wm = wid >> 1, wn = wid & 1;
    int bm = blockIdx.y * 128, bn = blockIdx.x * 64;

    float acc[2][4][4];
#pragma unroll
    for (int mt = 0; mt < 2; mt++)
#pragma unroll
        for (int nt = 0; nt < 4; nt++)
#pragma unroll
            for (int j = 0; j < 4; j++) acc[mt][nt][j] = 0.0f;

    // per-lane ldmatrix addresses (x4 blocks: m0k0, m8k0, m0k8, m8k8)
    int r8 = (l & 7) + ((l >> 3) & 1) * 8;
    int c8 = (l >> 4) * 8;
    uint32_t sb = smem_to_u32(smem);
    uint32_t aAH[2], aAL[2], aBH[2], aBL[2];
#pragma unroll
    for (int mt = 0; mt < 2; mt++) {
        uint32_t o = (uint32_t)(((wm * 32 + mt * 16 + r8) * ST + c8) * 2);
        aAH[mt] = sb + o;
        aAL[mt] = sb + A_SZ + o;
    }
#pragma unroll
    for (int nb = 0; nb < 2; nb++) {
        uint32_t o = (uint32_t)(((wn * 32 + nb * 16 + r8) * ST + c8) * 2);
        aBH[nb] = sb + 2 * A_SZ + o;
        aBL[nb] = sb + 2 * A_SZ + B_SZ + o;
    }

    for (int s = 0; s < NSTAGE; s++) {
        int k0 = s * TK;

        // ---- A tile 128 x TK: fp32 -> hi/lo bf16 (pairs, conflict-free)
        for (int idx = tid; idx < 128 * (TK / 2); idx += 256) {
            int row = idx / (TK / 2);
            int cp  = idx % (TK / 2);
            float2 v = make_float2(0.f, 0.f);
            int gr = bm + row;
            if (gr < M) v = *(const float2*)&A[(size_t)gr * KTOT + k0 + cp * 2];
            __nv_bfloat16 h0 = __float2bfloat16(v.x);
            __nv_bfloat16 h1 = __float2bfloat16(v.y);
            __nv_bfloat16 l0 = __float2bfloat16(v.x - __bfloat162float(h0));
            __nv_bfloat16 l1 = __float2bfloat16(v.y - __bfloat162float(h1));
            uint32_t hp = (uint32_t)__bfloat16_as_ushort(h0)
                        | ((uint32_t)__bfloat16_as_ushort(h1) << 16);
            uint32_t lp = (uint32_t)__bfloat16_as_ushort(l0)
                        | ((uint32_t)__bfloat16_as_ushort(l1) << 16);
            int off = row * ST + cp * 2;
            *(uint32_t*)(AH + off) = hp;
            *(uint32_t*)(AL + off) = lp;
        }
        // ---- B tile: Bs[n][k] = Bw[k0+k][bn+n], hi/lo
        for (int idx = tid; idx < TK * 64; idx += 256) {
            int k = idx >> 6;
            int n = idx & 63;
            float v = Bw[(size_t)(k0 + k) * NTOT + bn + n];
            __nv_bfloat16 h = __float2bfloat16(v);
            __nv_bfloat16 lo = __float2bfloat16(v - __bfloat162float(h));
            BH[n * ST + k] = h;
            BL[n * ST + k] = lo;
        }
        __syncthreads();

#pragma unroll
        for (int ks = 0; ks < TK / 16; ks++) {
            uint32_t koff = ks * 32;   // 16 bf16 * 2B
            uint32_t ah0[4], ah1[4], al0[4], al1[4];
            uint32_t bh0[4], bh1[4], bl0[4], bl1[4];
            ldsm_x4(ah0, aAH[0] + koff);
            ldsm_x4(ah1, aAH[1] + koff);
            ldsm_x4(al0, aAL[0] + koff);
            ldsm_x4(al1, aAL[1] + koff);
            ldsm_x4(bh0, aBH[0] + koff);
            ldsm_x4(bh1, aBH[1] + koff);
            ldsm_x4(bl0, aBL[0] + koff);
            ldsm_x4(bl1, aBL[1] + koff);
#pragma unroll
            for (int mt = 0; mt < 2; mt++) {
                const uint32_t* a_h = mt ? ah1 : ah0;
                const uint32_t* a_l = mt ? al1 : al0;
#pragma unroll
                for (int nt = 0; nt < 4; nt++) {
                    const uint32_t* b_h = (nt >> 1) ? bh1 : bh0;
                    const uint32_t* b_l = (nt >> 1) ? bl1 : bl0;
                    int sub = nt & 1;
                    mma_bf16(acc[mt][nt], a_h, b_h[sub], b_h[sub + 2]);
                    mma_bf16(acc[mt][nt], a_h, b_l[sub], b_l[sub + 2]);
                    mma_bf16(acc[mt][nt], a_l, b_h[sub], b_h[sub + 2]);
                }
            }
        }
        __syncthreads();
    }

    // ---- epilogue: c0,c1 -> (row g), c2,c3 -> (row g+8)
    int g = l >> 2, tg = l & 3;
#pragma unroll
    for (int mt = 0; mt < 2; mt++) {
        int row0 = bm + wm * 32 + mt * 16 + g;
#pragma unroll
        for (int nt = 0; nt < 4; nt++) {
            int col = bn + wn * 32 + nt * 8 + tg * 2;
            float bx = 0.f, by = 0.f;
            if (BIAS) {
                float2 bv = *(const float2*)&bias[col];
                bx = bv.x; by = bv.y;
            }
            float2 o0 = make_float2(acc[mt][nt][0] + bx, acc[mt][nt][1] + by);
            float2 o1 = make_float2(acc[mt][nt][2] + bx, acc[mt][nt][3] + by);
            if (RELU) {
                o0.x = fmaxf(o0.x, 0.f); o0.y = fmaxf(o0.y, 0.f);
                o1.x = fmaxf(o1.x, 0.f); o1.y = fmaxf(o1.y, 0.f);
            }
            if (row0 < M)
                *(float2*)&C[(size_t)row0 * NTOT + col] = o0;
            if (row0 + 8 < M)
                *(float2*)&C[(size_t)(row0 + 8) * NTOT + col] = o1;
        }
    }
}

// ---------------- init aggregation: agg[i] = h[i]*dinv[i]^2 (+ b) ----------
template<int C, bool BIAS>
__global__ void k_init_agg(const float* __restrict__ h,
                           const float* __restrict__ bias,
                           float* __restrict__ agg)
{
    const int V = C / 4;
    int idx = blockIdx.x * 256 + threadIdx.x;
    if (idx >= NN * V) return;
    int node = idx / V;
    int v    = idx % V;
    float di = g_dinv[node];
    float s  = di * di;
    float4 hv = ((const float4*)h)[(size_t)node * V + v];
    float4 o;
    if (BIAS) {
        float4 bv = ((const float4*)bias)[v];
        o.x = fmaf(hv.x, s, bv.x);
        o.y = fmaf(hv.y, s, bv.y);
        o.z = fmaf(hv.z, s, bv.z);
        o.w = fmaf(hv.w, s, bv.w);
    } else {
        o.x = hv.x * s; o.y = hv.y * s; o.z = hv.z * s; o.w = hv.w * s;
    }
    ((float4*)agg)[(size_t)node * V + v] = o;
}

// ---------------- edge scatter: agg[dst] += h[src] * dinv[src]*dinv[dst] ---
template<int C, int LPE>
__global__ void k_scatter(const int* __restrict__ src, const int* __restrict__ dst,
                          const float* __restrict__ h, float* __restrict__ agg)
{
    const int V = C / 4;
    int t   = blockIdx.x * 256 + threadIdx.x;
    int e   = t / LPE;
    int sub = t % LPE;
    if (e >= ECNT) return;
    int s = src[e];
    int d = dst[e];
    float norm = g_dinv[s] * g_dinv[d];
    const float4* hp = (const float4*)h   + (size_t)s * V;
    float4*       ap = (float4*)agg       + (size_t)d * V;
#pragma unroll
    for (int v = sub; v < V; v += LPE) {
        float4 hv = hp[v];
        float mx = hv.x * norm, my = hv.y * norm, mz = hv.z * norm, mw = hv.w * norm;
        asm volatile("red.global.add.v4.f32 [%0], {%1, %2, %3, %4};"
                     :: "l"(ap + v), "f"(mx), "f"(my), "f"(mz), "f"(mw)
                     : "memory");
    }
}

// ---------------- launch ---------------------------------------------------
extern "C" void kernel_launch(void* const* d_in, const int* in_sizes, int n_in,
                              void* d_out, int out_size)
{
    const float* x   = (const float*)d_in[0];
    const int*   ei  = (const int*)  d_in[1];
    const float* W1  = (const float*)d_in[2];
    const float* b1  = (const float*)d_in[3];
    const float* W2  = (const float*)d_in[4];
    const float* b2  = (const float*)d_in[5];
    const float* Wd1 = (const float*)d_in[6];
    const float* bd1 = (const float*)d_in[7];
    const float* Wd2 = (const float*)d_in[8];
    const float* bd2 = (const float*)d_in[9];
    float* out = (float*)d_out;

    const int* srcp = ei;
    const int* dstp = ei + ECNT;

    float *p_aggx, *p_h1r, *p_h2, *p_z, *p_d;
    cudaGetSymbolAddress((void**)&p_aggx, g_aggx);
    cudaGetSymbolAddress((void**)&p_h1r,  g_h1r);
    cudaGetSymbolAddress((void**)&p_h2,   g_h2);
    cudaGetSymbolAddress((void**)&p_z,    g_z);
    cudaGetSymbolAddress((void**)&p_d,    g_d);

    const int SMEM = 2 * (128 * 72 * 2) + 2 * (64 * 72 * 2);  // 55296 B
    cudaFuncSetAttribute((const void*)k_gemm_mma<128, true,  true >,
                         cudaFuncAttributeMaxDynamicSharedMemorySize, SMEM);
    cudaFuncSetAttribute((const void*)k_gemm_mma<256, false, false>,
                         cudaFuncAttributeMaxDynamicSharedMemorySize, SMEM);
    cudaFuncSetAttribute((const void*)k_gemm_mma<64,  true,  true >,
                         cudaFuncAttributeMaxDynamicSharedMemorySize, SMEM);
    cudaFuncSetAttribute((const void*)k_gemm_mma<256, true,  false>,
                         cudaFuncAttributeMaxDynamicSharedMemorySize, SMEM);

    // --- degree + normalization
    k_deg_init <<<(NN   + 255) / 256, 256>>>();
    k_deg_count<<<(ECNT + 255) / 256, 256>>>(dstp);
    k_dinv     <<<(NN   + 255) / 256, 256>>>();

    const int MB = (NN + 127) / 128;   // 391 row-blocks

    // --- layer 1: aggx = Dsym-scatter(x);  h1r = relu(aggx@W1 + b1)
    k_init_agg<128,false><<<(NN * 32 + 255) / 256, 256>>>(x, nullptr, p_aggx);
    k_scatter<128,32><<<(ECNT * 32) / 256, 256>>>(srcp, dstp, x, p_aggx);
    k_gemm_mma<128, true, true><<<dim3(4, MB), 256, SMEM>>>(p_aggx, W1, b1, p_h1r, 256);

    // --- layer 2: h2 = h1r @ W2 ; z = scatter(h2) + b2
    k_gemm_mma<256, false, false><<<dim3(1, MB), 256, SMEM>>>(p_h1r, W2, nullptr, p_h2, 64);
    k_init_agg<64,true><<<(NN * 16 + 255) / 256, 256>>>(p_h2, b2, p_z);
    k_scatter<64,16><<<(ECNT * 16) / 256, 256>>>(srcp, dstp, p_h2, p_z);

    // --- decoder: d = relu(z @ Wd1 + bd1) ; out = d @ Wd2 + bd2
    k_gemm_mma<64, true, true><<<dim3(4, MB), 256, SMEM>>>(p_z, Wd1, bd1, p_d, 256);
    k_gemm_mma<256, true, false><<<dim3(2, MB), 256, SMEM>>>(p_d, Wd2, bd2, out, 128);
}

// round 5
// speedup vs baseline: 1.7221x; 1.7221x over previous
#include <cuda_runtime.h>
#include <cuda_bf16.h>
#include <cstdint>

#define NN   50000
#define ECNT 800000

// ===================== helpers =============================================
__device__ __forceinline__ uint32_t smem_to_u32(const void* p) {
    uint32_t a;
    asm("{ .reg .u64 t; cvta.to.shared.u64 t, %1; cvt.u32.u64 %0, t; }"
        : "=r"(a) : "l"(p));
    return a;
}
__device__ __forceinline__ void ldsm_x4(uint32_t* r, uint32_t addr) {
    asm volatile("ldmatrix.sync.aligned.m8n8.x4.shared.b16 {%0,%1,%2,%3}, [%4];"
        : "=r"(r[0]), "=r"(r[1]), "=r"(r[2]), "=r"(r[3]) : "r"(addr));
}
__device__ __forceinline__ void mma_bf16(float* c, const uint32_t* a,
                                         uint32_t b0, uint32_t b1) {
    asm volatile("mma.sync.aligned.m16n8k16.row.col.f32.bf16.bf16.f32 "
        "{%0,%1,%2,%3}, {%4,%5,%6,%7}, {%8,%9}, {%0,%1,%2,%3};"
        : "+f"(c[0]), "+f"(c[1]), "+f"(c[2]), "+f"(c[3])
        : "r"(a[0]), "r"(a[1]), "r"(a[2]), "r"(a[3]), "r"(b0), "r"(b1));
}
__device__ __forceinline__ void cp16(uint32_t dst, const void* src) {
    asm volatile("cp.async.cg.shared.global [%0], [%1], 16;"
                 :: "r"(dst), "l"(src) : "memory");
}
__device__ __forceinline__ void cp_commit_wait() {
    asm volatile("cp.async.commit_group;" ::: "memory");
    asm volatile("cp.async.wait_group 0;" ::: "memory");
}
__device__ __forceinline__ uint32_t split_pack_hi(float a, float b,
                                                  uint32_t& lo_pack) {
    __nv_bfloat16 h0 = __float2bfloat16(a);
    __nv_bfloat16 h1 = __float2bfloat16(b);
    __nv_bfloat16 l0 = __float2bfloat16(a - __bfloat162float(h0));
    __nv_bfloat16 l1 = __float2bfloat16(b - __bfloat162float(h1));
    lo_pack = (uint32_t)__bfloat16_as_ushort(l0)
            | ((uint32_t)__bfloat16_as_ushort(l1) << 16);
    return (uint32_t)__bfloat16_as_ushort(h0)
         | ((uint32_t)__bfloat16_as_ushort(h1) << 16);
}

// ---------------- scratch (device globals; no allocation allowed) ----------
__device__ float g_deg [NN];
__device__ float g_dinv[NN];
__device__ float g_aggx[(size_t)NN * 128];
__device__ float g_h2  [(size_t)NN * 64];
__device__ float g_z   [(size_t)NN * 64];
__device__ __nv_bfloat16 g_axh[(size_t)NN * 128], g_axl[(size_t)NN * 128];
__device__ __nv_bfloat16 g_h1h[(size_t)NN * 256], g_h1l[(size_t)NN * 256];
__device__ __nv_bfloat16 g_zh [(size_t)NN * 64],  g_zl [(size_t)NN * 64];
__device__ __nv_bfloat16 g_dh [(size_t)NN * 256], g_dl [(size_t)NN * 256];
__device__ __nv_bfloat16 g_w1h[256 * 128],  g_w1l[256 * 128];   // [N][K]
__device__ __nv_bfloat16 g_w2h[64 * 256],   g_w2l[64 * 256];
__device__ __nv_bfloat16 g_wd1h[256 * 64],  g_wd1l[256 * 64];
__device__ __nv_bfloat16 g_wd2h[128 * 256], g_wd2l[128 * 256];

// ---------------- degree / normalization ----------------------------------
__global__ void k_deg_init() {
    int i = blockIdx.x * 256 + threadIdx.x;
    if (i < NN) g_deg[i] = 1.0f;
}
__global__ void k_deg_count(const int* __restrict__ dst) {
    int e = blockIdx.x * 256 + threadIdx.x;
    if (e < ECNT) atomicAdd(&g_deg[dst[e]], 1.0f);
}
__global__ void k_dinv() {
    int i = blockIdx.x * 256 + threadIdx.x;
    if (i < NN) g_dinv[i] = rsqrtf(g_deg[i]);
}

// ---------------- fp32 -> bf16 hi/lo split (flat, vectorized) --------------
__global__ void k_split(const float* __restrict__ in,
                        __nv_bfloat16* __restrict__ oh,
                        __nv_bfloat16* __restrict__ ol, int n4)
{
    int i = blockIdx.x * 256 + threadIdx.x;
    if (i >= n4) return;
    float4 v = ((const float4*)in)[i];
    uint32_t l0, l1;
    uint32_t h0 = split_pack_hi(v.x, v.y, l0);
    uint32_t h1 = split_pack_hi(v.z, v.w, l1);
    ((uint2*)oh)[i] = make_uint2(h0, h1);
    ((uint2*)ol)[i] = make_uint2(l0, l1);
}

// ---------------- weight [K x N] fp32 -> transposed hi/lo [N x K] bf16 -----
__global__ void k_split_wT(const float* __restrict__ W,
                           __nv_bfloat16* __restrict__ th,
                           __nv_bfloat16* __restrict__ tl, int K, int N)
{
    int idx = blockIdx.x * 256 + threadIdx.x;
    if (idx >= K * N) return;
    int k = idx / N, n = idx % N;
    float v = W[idx];
    __nv_bfloat16 h = __float2bfloat16(v);
    th[n * K + k] = h;
    tl[n * K + k] = __float2bfloat16(v - __bfloat162float(h));
}

// ============ bf16x3 tensor-core GEMM (preconverted operands) ==============
// CTA tile 128x64, 8 warps (4m x 2n), warp 32x32 = 2x4 m16n8k16 tiles.
// A: [M x KTOT] hi/lo bf16 k-major. B: [NTOT x KTOT] hi/lo bf16 k-major.
// acc += Ah*Bh + Ah*Bl + Al*Bh (fp32). Output fp32 or hi/lo-split bf16.
template<int KTOT, int NTOT, bool BIAS, bool RELU, bool SPLIT>
__global__ void __launch_bounds__(256, 2)
k_gemm_bf(const __nv_bfloat16* __restrict__ Ah, const __nv_bfloat16* __restrict__ Al,
          const __nv_bfloat16* __restrict__ Bh, const __nv_bfloat16* __restrict__ Bl,
          const float* __restrict__ bias, float* __restrict__ Cf,
          __nv_bfloat16* __restrict__ Ch, __nv_bfloat16* __restrict__ Cl)
{
    constexpr int M  = NN;
    constexpr int TK = 64;
    constexpr int ST = 72;                    // 144B row stride (16B aligned)
    constexpr int NSTAGE = KTOT / TK;
    constexpr int A_SZ = 128 * ST * 2;        // 18432 B
    constexpr int B_SZ = 64 * ST * 2;         //  9216 B

    extern __shared__ char smem[];
    uint32_t sb = smem_to_u32(smem);
    int tid = threadIdx.x, l = tid & 31, wid = tid >> 5;
    int wm = wid >> 1, wn = wid & 1;
    int bm = blockIdx.y * 128, bn = blockIdx.x * 64;

    float acc[2][4][4];
#pragma unroll
    for (int mt = 0; mt < 2; mt++)
#pragma unroll
        for (int nt = 0; nt < 4; nt++)
#pragma unroll
            for (int j = 0; j < 4; j++) acc[mt][nt][j] = 0.0f;

    // per-lane ldmatrix addresses (x4 blocks: m0k0, m8k0, m0k8, m8k8)
    int r8 = (l & 7) + ((l >> 3) & 1) * 8;
    int c8 = (l >> 4) * 8;
    uint32_t aAH[2], aAL[2], aBH[2], aBL[2];
#pragma unroll
    for (int mt = 0; mt < 2; mt++) {
        uint32_t o = (uint32_t)(((wm * 32 + mt * 16 + r8) * ST + c8) * 2);
        aAH[mt] = sb + o;
        aAL[mt] = sb + A_SZ + o;
    }
#pragma unroll
    for (int nb = 0; nb < 2; nb++) {
        uint32_t o = (uint32_t)(((wn * 32 + nb * 16 + r8) * ST + c8) * 2);
        aBH[nb] = sb + 2 * A_SZ + o;
        aBL[nb] = sb + 2 * A_SZ + B_SZ + o;
    }

    for (int s = 0; s < NSTAGE; s++) {
        int k0 = s * TK;
        // ---- A tiles via cp.async: 128 rows x 8 chunks(16B) x {H,L}
#pragma unroll
        for (int it = 0; it < 8; it++) {
            int i   = tid + it * 256;        // 0..2047
            int row = i >> 4;
            int sub = i & 15;
            int arr = sub >> 3;
            int ch  = sub & 7;
            int gr  = bm + row;
            if (gr < M) {
                const __nv_bfloat16* src =
                    (arr ? Al : Ah) + (size_t)gr * KTOT + k0 + ch * 8;
                cp16(sb + arr * A_SZ + row * (ST * 2) + ch * 16, src);
            }
        }
        // ---- B tiles: 64 rows x 8 chunks x {H,L}
#pragma unroll
        for (int it = 0; it < 4; it++) {
            int i   = tid + it * 256;        // 0..1023
            int n   = i >> 4;
            int sub = i & 15;
            int arr = sub >> 3;
            int ch  = sub & 7;
            const __nv_bfloat16* src =
                (arr ? Bl : Bh) + (size_t)(bn + n) * KTOT + k0 + ch * 8;
            cp16(sb + 2 * A_SZ + arr * B_SZ + n * (ST * 2) + ch * 16, src);
        }
        cp_commit_wait();
        __syncthreads();

#pragma unroll
        for (int ks = 0; ks < TK / 16; ks++) {
            uint32_t koff = ks * 32;
            uint32_t ah0[4], ah1[4], al0[4], al1[4];
            uint32_t bh0[4], bh1[4], bl0[4], bl1[4];
            ldsm_x4(ah0, aAH[0] + koff);
            ldsm_x4(ah1, aAH[1] + koff);
            ldsm_x4(al0, aAL[0] + koff);
            ldsm_x4(al1, aAL[1] + koff);
            ldsm_x4(bh0, aBH[0] + koff);
            ldsm_x4(bh1, aBH[1] + koff);
            ldsm_x4(bl0, aBL[0] + koff);
            ldsm_x4(bl1, aBL[1] + koff);
#pragma unroll
            for (int mt = 0; mt < 2; mt++) {
                const uint32_t* a_h = mt ? ah1 : ah0;
                const uint32_t* a_l = mt ? al1 : al0;
#pragma unroll
                for (int nt = 0; nt < 4; nt++) {
                    const uint32_t* b_h = (nt >> 1) ? bh1 : bh0;
                    const uint32_t* b_l = (nt >> 1) ? bl1 : bl0;
                    int sub = nt & 1;
                    mma_bf16(acc[mt][nt], a_h, b_h[sub], b_h[sub + 2]);
                    mma_bf16(acc[mt][nt], a_h, b_l[sub], b_l[sub + 2]);
                    mma_bf16(acc[mt][nt], a_l, b_h[sub], b_h[sub + 2]);
                }
            }
        }
        __syncthreads();
    }

    // ---- epilogue
    int g = l >> 2, tg = l & 3;
#pragma unroll
    for (int mt = 0; mt < 2; mt++) {
        int row0 = bm + wm * 32 + mt * 16 + g;
#pragma unroll
        for (int nt = 0; nt < 4; nt++) {
            int col = bn + wn * 32 + nt * 8 + tg * 2;
            float bx = 0.f, by = 0.f;
            if (BIAS) {
                float2 bv = *(const float2*)&bias[col];
                bx = bv.x; by = bv.y;
            }
            float2 o0 = make_float2(acc[mt][nt][0] + bx, acc[mt][nt][1] + by);
            float2 o1 = make_float2(acc[mt][nt][2] + bx, acc[mt][nt][3] + by);
            if (RELU) {
                o0.x = fmaxf(o0.x, 0.f); o0.y = fmaxf(o0.y, 0.f);
                o1.x = fmaxf(o1.x, 0.f); o1.y = fmaxf(o1.y, 0.f);
            }
            if (SPLIT) {
                uint32_t lp;
                if (row0 < M) {
                    uint32_t hp = split_pack_hi(o0.x, o0.y, lp);
                    *(uint32_t*)&Ch[(size_t)row0 * NTOT + col] = hp;
                    *(uint32_t*)&Cl[(size_t)row0 * NTOT + col] = lp;
                }
                if (row0 + 8 < M) {
                    uint32_t hp = split_pack_hi(o1.x, o1.y, lp);
                    *(uint32_t*)&Ch[(size_t)(row0 + 8) * NTOT + col] = hp;
                    *(uint32_t*)&Cl[(size_t)(row0 + 8) * NTOT + col] = lp;
                }
            } else {
                if (row0 < M)
                    *(float2*)&Cf[(size_t)row0 * NTOT + col] = o0;
                if (row0 + 8 < M)
                    *(float2*)&Cf[(size_t)(row0 + 8) * NTOT + col] = o1;
            }
        }
    }
}

// ---------------- init aggregation: agg[i] = h[i]*dinv[i]^2 (+ b) ----------
template<int C, bool BIAS>
__global__ void k_init_agg(const float* __restrict__ h,
                           const float* __restrict__ bias,
                           float* __restrict__ agg)
{
    const int V = C / 4;
    int idx = blockIdx.x * 256 + threadIdx.x;
    if (idx >= NN * V) return;
    int node = idx / V;
    int v    = idx % V;
    float di = g_dinv[node];
    float s  = di * di;
    float4 hv = ((const float4*)h)[(size_t)node * V + v];
    float4 o;
    if (BIAS) {
        float4 bv = ((const float4*)bias)[v];
        o.x = fmaf(hv.x, s, bv.x);
        o.y = fmaf(hv.y, s, bv.y);
        o.z = fmaf(hv.z, s, bv.z);
        o.w = fmaf(hv.w, s, bv.w);
    } else {
        o.x = hv.x * s; o.y = hv.y * s; o.z = hv.z * s; o.w = hv.w * s;
    }
    ((float4*)agg)[(size_t)node * V + v] = o;
}

// ---------------- edge scatter: agg[dst] += h[src] * dinv[src]*dinv[dst] ---
template<int C, int LPE>
__global__ void k_scatter(const int* __restrict__ src, const int* __restrict__ dst,
                          const float* __restrict__ h, float* __restrict__ agg)
{
    const int V = C / 4;
    int t   = blockIdx.x * 256 + threadIdx.x;
    int e   = t / LPE;
    int sub = t % LPE;
    if (e >= ECNT) return;
    int s = src[e];
    int d = dst[e];
    float norm = g_dinv[s] * g_dinv[d];
    const float4* hp = (const float4*)h   + (size_t)s * V;
    float4*       ap = (float4*)agg       + (size_t)d * V;
#pragma unroll
    for (int v = sub; v < V; v += LPE) {
        float4 hv = hp[v];
        float mx = hv.x * norm, my = hv.y * norm, mz = hv.z * norm, mw = hv.w * norm;
        asm volatile("red.global.add.v4.f32 [%0], {%1, %2, %3, %4};"
                     :: "l"(ap + v), "f"(mx), "f"(my), "f"(mz), "f"(mw)
                     : "memory");
    }
}

// ---------------- launch ---------------------------------------------------
extern "C" void kernel_launch(void* const* d_in, const int* in_sizes, int n_in,
                              void* d_out, int out_size)
{
    const float* x   = (const float*)d_in[0];
    const int*   ei  = (const int*)  d_in[1];
    const float* W1  = (const float*)d_in[2];
    const float* b1  = (const float*)d_in[3];
    const float* W2  = (const float*)d_in[4];
    const float* b2  = (const float*)d_in[5];
    const float* Wd1 = (const float*)d_in[6];
    const float* bd1 = (const float*)d_in[7];
    const float* Wd2 = (const float*)d_in[8];
    const float* bd2 = (const float*)d_in[9];
    float* out = (float*)d_out;

    const int* srcp = ei;
    const int* dstp = ei + ECNT;

    float *p_aggx, *p_h2, *p_z;
    cudaGetSymbolAddress((void**)&p_aggx, g_aggx);
    cudaGetSymbolAddress((void**)&p_h2,   g_h2);
    cudaGetSymbolAddress((void**)&p_z,    g_z);
    __nv_bfloat16 *p_axh, *p_axl, *p_h1h, *p_h1l, *p_zh, *p_zl, *p_dh, *p_dl;
    __nv_bfloat16 *p_w1h, *p_w1l, *p_w2h, *p_w2l, *p_wd1h, *p_wd1l, *p_wd2h, *p_wd2l;
    cudaGetSymbolAddress((void**)&p_axh, g_axh);
    cudaGetSymbolAddress((void**)&p_axl, g_axl);
    cudaGetSymbolAddress((void**)&p_h1h, g_h1h);
    cudaGetSymbolAddress((void**)&p_h1l, g_h1l);
    cudaGetSymbolAddress((void**)&p_zh,  g_zh);
    cudaGetSymbolAddress((void**)&p_zl,  g_zl);
    cudaGetSymbolAddress((void**)&p_dh,  g_dh);
    cudaGetSymbolAddress((void**)&p_dl,  g_dl);
    cudaGetSymbolAddress((void**)&p_w1h, g_w1h);
    cudaGetSymbolAddress((void**)&p_w1l, g_w1l);
    cudaGetSymbolAddress((void**)&p_w2h, g_w2h);
    cudaGetSymbolAddress((void**)&p_w2l, g_w2l);
    cudaGetSymbolAddress((void**)&p_wd1h, g_wd1h);
    cudaGetSymbolAddress((void**)&p_wd1l, g_wd1l);
    cudaGetSymbolAddress((void**)&p_wd2h, g_wd2h);
    cudaGetSymbolAddress((void**)&p_wd2l, g_wd2l);

    const int SMEM = 2 * (128 * 72 * 2) + 2 * (64 * 72 * 2);  // 55296 B
    cudaFuncSetAttribute((const void*)k_gemm_bf<128, 256, true,  true,  true >,
                         cudaFuncAttributeMaxDynamicSharedMemorySize, SMEM);
    cudaFuncSetAttribute((const void*)k_gemm_bf<256, 64,  false, false, false>,
                         cudaFuncAttributeMaxDynamicSharedMemorySize, SMEM);
    cudaFuncSetAttribute((const void*)k_gemm_bf<64,  256, true,  true,  true >,
                         cudaFuncAttributeMaxDynamicSharedMemorySize, SMEM);
    cudaFuncSetAttribute((const void*)k_gemm_bf<256, 128, true,  false, false>,
                         cudaFuncAttributeMaxDynamicSharedMemorySize, SMEM);

    // --- weights: split + transpose (tiny)
    k_split_wT<<<(128 * 256 + 255) / 256, 256>>>(W1,  p_w1h,  p_w1l,  128, 256);
    k_split_wT<<<(256 * 64  + 255) / 256, 256>>>(W2,  p_w2h,  p_w2l,  256, 64);
    k_split_wT<<<(64  * 256 + 255) / 256, 256>>>(Wd1, p_wd1h, p_wd1l, 64,  256);
    k_split_wT<<<(256 * 128 + 255) / 256, 256>>>(Wd2, p_wd2h, p_wd2l, 256, 128);

    // --- degree + normalization
    k_deg_init <<<(NN   + 255) / 256, 256>>>();
    k_deg_count<<<(ECNT + 255) / 256, 256>>>(dstp);
    k_dinv     <<<(NN   + 255) / 256, 256>>>();

    const int MB = (NN + 127) / 128;   // 391 row-blocks

    // --- layer 1: aggx = Dsym-scatter(x); split; h1 = relu(aggx@W1+b1) [bf16 hi/lo]
    k_init_agg<128,false><<<(NN * 32 + 255) / 256, 256>>>(x, nullptr, p_aggx);
    k_scatter<128,32><<<(ECNT * 32) / 256, 256>>>(srcp, dstp, x, p_aggx);
    k_split<<<(NN * 32 + 255) / 256, 256>>>(p_aggx, p_axh, p_axl, NN * 32);
    k_gemm_bf<128, 256, true, true, true><<<dim3(4, MB), 256, SMEM>>>(
        p_axh, p_axl, p_w1h, p_w1l, b1, nullptr, p_h1h, p_h1l);

    // --- layer 2: h2 = h1 @ W2 [fp32]; z = scatter(h2) + b2; split
    k_gemm_bf<256, 64, false, false, false><<<dim3(1, MB), 256, SMEM>>>(
        p_h1h, p_h1l, p_w2h, p_w2l, nullptr, p_h2, nullptr, nullptr);
    k_init_agg<64,true><<<(NN * 16 + 255) / 256, 256>>>(p_h2, b2, p_z);
    k_scatter<64,16><<<(ECNT * 16) / 256, 256>>>(srcp, dstp, p_h2, p_z);
    k_split<<<(NN * 16 + 255) / 256, 256>>>(p_z, p_zh, p_zl, NN * 16);

    // --- decoder: d = relu(z @ Wd1 + bd1) [bf16 hi/lo]; out = d @ Wd2 + bd2
    k_gemm_bf<64, 256, true, true, true><<<dim3(4, MB), 256, SMEM>>>(
        p_zh, p_zl, p_wd1h, p_wd1l, bd1, nullptr, p_dh, p_dl);
    k_gemm_bf<256, 128, true, false, false><<<dim3(2, MB), 256, SMEM>>>(
        p_dh, p_dl, p_wd2h, p_wd2l, bd2, out, nullptr, nullptr);
}

// round 6
// speedup vs baseline: 1.8199x; 1.0568x over previous
#include <cuda_runtime.h>
#include <cuda_bf16.h>
#include <cstdint>

#define NN   50000
#define ECNT 800000

// ===================== helpers =============================================
__device__ __forceinline__ uint32_t smem_to_u32(const void* p) {
    uint32_t a;
    asm("{ .reg .u64 t; cvta.to.shared.u64 t, %1; cvt.u32.u64 %0, t; }"
        : "=r"(a) : "l"(p));
    return a;
}
__device__ __forceinline__ void ldsm_x4(uint32_t* r, uint32_t addr) {
    asm volatile("ldmatrix.sync.aligned.m8n8.x4.shared.b16 {%0,%1,%2,%3}, [%4];"
        : "=r"(r[0]), "=r"(r[1]), "=r"(r[2]), "=r"(r[3]) : "r"(addr));
}
__device__ __forceinline__ void mma_bf16(float* c, const uint32_t* a,
                                         uint32_t b0, uint32_t b1) {
    asm volatile("mma.sync.aligned.m16n8k16.row.col.f32.bf16.bf16.f32 "
        "{%0,%1,%2,%3}, {%4,%5,%6,%7}, {%8,%9}, {%0,%1,%2,%3};"
        : "+f"(c[0]), "+f"(c[1]), "+f"(c[2]), "+f"(c[3])
        : "r"(a[0]), "r"(a[1]), "r"(a[2]), "r"(a[3]), "r"(b0), "r"(b1));
}
__device__ __forceinline__ void cp16(uint32_t dst, const void* src) {
    asm volatile("cp.async.cg.shared.global [%0], [%1], 16;"
                 :: "r"(dst), "l"(src) : "memory");
}
__device__ __forceinline__ void cp_commit() {
    asm volatile("cp.async.commit_group;" ::: "memory");
}
template<int N>
__device__ __forceinline__ void cp_wait() {
    asm volatile("cp.async.wait_group %0;" :: "n"(N) : "memory");
}
__device__ __forceinline__ uint32_t split_pack_hi(float a, float b,
                                                  uint32_t& lo_pack) {
    __nv_bfloat16 h0 = __float2bfloat16(a);
    __nv_bfloat16 h1 = __float2bfloat16(b);
    __nv_bfloat16 l0 = __float2bfloat16(a - __bfloat162float(h0));
    __nv_bfloat16 l1 = __float2bfloat16(b - __bfloat162float(h1));
    lo_pack = (uint32_t)__bfloat16_as_ushort(l0)
            | ((uint32_t)__bfloat16_as_ushort(l1) << 16);
    return (uint32_t)__bfloat16_as_ushort(h0)
         | ((uint32_t)__bfloat16_as_ushort(h1) << 16);
}

// ---------------- scratch (device globals; no allocation allowed) ----------
__device__ float g_deg [NN];
__device__ float g_dinv[NN];
__device__ float g_aggx[(size_t)NN * 128];
__device__ float g_h2  [(size_t)NN * 64];
__device__ float g_z   [(size_t)NN * 64];
__device__ __nv_bfloat16 g_axh[(size_t)NN * 128], g_axl[(size_t)NN * 128];
__device__ __nv_bfloat16 g_h1h[(size_t)NN * 256], g_h1l[(size_t)NN * 256];
__device__ __nv_bfloat16 g_zh [(size_t)NN * 64],  g_zl [(size_t)NN * 64];
__device__ __nv_bfloat16 g_dh [(size_t)NN * 256], g_dl [(size_t)NN * 256];
__device__ __nv_bfloat16 g_w1h[256 * 128],  g_w1l[256 * 128];   // [N][K]
__device__ __nv_bfloat16 g_w2h[64 * 256],   g_w2l[64 * 256];
__device__ __nv_bfloat16 g_wd1h[256 * 64],  g_wd1l[256 * 64];
__device__ __nv_bfloat16 g_wd2h[128 * 256], g_wd2l[128 * 256];

// ---------------- prep: all 4 weight splits (transposed) + deg init --------
__device__ __forceinline__ void splitw(const float* W, __nv_bfloat16* th,
                                       __nv_bfloat16* tl, int i, int K, int N) {
    int k = i / N, n = i % N;
    float v = W[i];
    __nv_bfloat16 h = __float2bfloat16(v);
    th[n * K + k] = h;
    tl[n * K + k] = __float2bfloat16(v - __bfloat162float(h));
}
__global__ void k_prep(const float* __restrict__ W1, const float* __restrict__ W2,
                       const float* __restrict__ Wd1, const float* __restrict__ Wd2)
{
    int i = blockIdx.x * 256 + threadIdx.x;
    if (i < 32768) {
        splitw(W1, g_w1h, g_w1l, i, 128, 256);
    } else if (i < 49152) {
        splitw(W2, g_w2h, g_w2l, i - 32768, 256, 64);
    } else if (i < 65536) {
        splitw(Wd1, g_wd1h, g_wd1l, i - 49152, 64, 256);
    } else if (i < 98304) {
        splitw(Wd2, g_wd2h, g_wd2l, i - 65536, 256, 128);
    } else {
        int n = i - 98304;
        if (n < NN) g_deg[n] = 1.0f;     // self-loop contributes 1
    }
}
__global__ void k_deg_count(const int* __restrict__ dst) {
    int e = blockIdx.x * 256 + threadIdx.x;
    if (e < ECNT) atomicAdd(&g_deg[dst[e]], 1.0f);
}

// ---------------- fp32 -> bf16 hi/lo split (flat, vectorized) --------------
__global__ void k_split(const float* __restrict__ in,
                        __nv_bfloat16* __restrict__ oh,
                        __nv_bfloat16* __restrict__ ol, int n4)
{
    int i = blockIdx.x * 256 + threadIdx.x;
    if (i >= n4) return;
    float4 v = ((const float4*)in)[i];
    uint32_t l0, l1;
    uint32_t h0 = split_pack_hi(v.x, v.y, l0);
    uint32_t h1 = split_pack_hi(v.z, v.w, l1);
    ((uint2*)oh)[i] = make_uint2(h0, h1);
    ((uint2*)ol)[i] = make_uint2(l0, l1);
}

// ============ bf16x3 tensor-core GEMM, 2-stage cp.async pipeline ===========
// CTA tile 128x64, 8 warps (4m x 2n), warp 32x32 = 2x4 m16n8k16 tiles.
// A: [M x KTOT] hi/lo bf16 k-major. B: [NTOT x KTOT] hi/lo bf16 k-major.
// acc += Ah*Bh + Ah*Bl + Al*Bh (fp32). Output fp32 or hi/lo-split bf16.
template<int KTOT, int NTOT, bool BIAS, bool RELU, bool SPLIT>
__global__ void __launch_bounds__(256, 2)
k_gemm_bf(const __nv_bfloat16* __restrict__ Ah, const __nv_bfloat16* __restrict__ Al,
          const __nv_bfloat16* __restrict__ Bh, const __nv_bfloat16* __restrict__ Bl,
          const float* __restrict__ bias, float* __restrict__ Cf,
          __nv_bfloat16* __restrict__ Ch, __nv_bfloat16* __restrict__ Cl)
{
    constexpr int M  = NN;
    constexpr int TK = 64;
    constexpr int ST = 72;                    // 144B row stride (16B aligned)
    constexpr int NSTAGE = KTOT / TK;
    constexpr int A_SZ = 128 * ST * 2;        // 18432 B
    constexpr int B_SZ = 64 * ST * 2;         //  9216 B
    constexpr int STG  = 2 * A_SZ + 2 * B_SZ; // 55296 B per stage
    constexpr int PIPE = (NSTAGE > 1) ? 2 : 1;

    extern __shared__ char smem[];
    uint32_t sb = smem_to_u32(smem);
    int tid = threadIdx.x, l = tid & 31, wid = tid >> 5;
    int wm = wid >> 1, wn = wid & 1;
    int bm = blockIdx.y * 128, bn = blockIdx.x * 64;

    float acc[2][4][4];
#pragma unroll
    for (int mt = 0; mt < 2; mt++)
#pragma unroll
        for (int nt = 0; nt < 4; nt++)
#pragma unroll
            for (int j = 0; j < 4; j++) acc[mt][nt][j] = 0.0f;

    // per-lane ldmatrix base offsets (x4 blocks: m0k0, m8k0, m0k8, m8k8)
    int r8 = (l & 7) + ((l >> 3) & 1) * 8;
    int c8 = (l >> 4) * 8;
    uint32_t aAH[2], aAL[2], aBH[2], aBL[2];
#pragma unroll
    for (int mt = 0; mt < 2; mt++) {
        uint32_t o = (uint32_t)(((wm * 32 + mt * 16 + r8) * ST + c8) * 2);
        aAH[mt] = sb + o;
        aAL[mt] = sb + A_SZ + o;
    }
#pragma unroll
    for (int nb = 0; nb < 2; nb++) {
        uint32_t o = (uint32_t)(((wn * 32 + nb * 16 + r8) * ST + c8) * 2);
        aBH[nb] = sb + 2 * A_SZ + o;
        aBL[nb] = sb + 2 * A_SZ + B_SZ + o;
    }

    // ---- stage loader (cp.async, 16B) ----
    auto load_stage = [&](int s, int buf) {
        int k0 = s * TK;
        uint32_t base = sb + buf * STG;
#pragma unroll
        for (int it = 0; it < 8; it++) {
            int i   = tid + it * 256;        // 0..2047
            int row = i >> 4;
            int sub = i & 15;
            int arr = sub >> 3;
            int ch  = sub & 7;
            int gr  = bm + row;
            if (gr < M) {
                const __nv_bfloat16* src =
                    (arr ? Al : Ah) + (size_t)gr * KTOT + k0 + ch * 8;
                cp16(base + arr * A_SZ + row * (ST * 2) + ch * 16, src);
            }
        }
#pragma unroll
        for (int it = 0; it < 4; it++) {
            int i   = tid + it * 256;        // 0..1023
            int n   = i >> 4;
            int sub = i & 15;
            int arr = sub >> 3;
            int ch  = sub & 7;
            const __nv_bfloat16* src =
                (arr ? Bl : Bh) + (size_t)(bn + n) * KTOT + k0 + ch * 8;
            cp16(base + 2 * A_SZ + arr * B_SZ + n * (ST * 2) + ch * 16, src);
        }
        cp_commit();
    };

    load_stage(0, 0);

    for (int s = 0; s < NSTAGE; s++) {
        int buf = (PIPE == 2) ? (s & 1) : 0;
        if (PIPE == 2 && s + 1 < NSTAGE) load_stage(s + 1, buf ^ 1);
        if (PIPE == 2 && s + 1 < NSTAGE) cp_wait<1>(); else cp_wait<0>();
        __syncthreads();

        uint32_t bo = buf * STG;
#pragma unroll
        for (int ks = 0; ks < TK / 16; ks++) {
            uint32_t koff = bo + ks * 32;
            uint32_t ah0[4], ah1[4], al0[4], al1[4];
            uint32_t bh0[4], bh1[4], bl0[4], bl1[4];
            ldsm_x4(ah0, aAH[0] + koff);
            ldsm_x4(ah1, aAH[1] + koff);
            ldsm_x4(al0, aAL[0] + koff);
            ldsm_x4(al1, aAL[1] + koff);
            ldsm_x4(bh0, aBH[0] + koff);
            ldsm_x4(bh1, aBH[1] + koff);
            ldsm_x4(bl0, aBL[0] + koff);
            ldsm_x4(bl1, aBL[1] + koff);
#pragma unroll
            for (int mt = 0; mt < 2; mt++) {
                const uint32_t* a_h = mt ? ah1 : ah0;
                const uint32_t* a_l = mt ? al1 : al0;
#pragma unroll
                for (int nt = 0; nt < 4; nt++) {
                    const uint32_t* b_h = (nt >> 1) ? bh1 : bh0;
                    const uint32_t* b_l = (nt >> 1) ? bl1 : bl0;
                    int sub = nt & 1;
                    mma_bf16(acc[mt][nt], a_h, b_h[sub], b_h[sub + 2]);
                    mma_bf16(acc[mt][nt], a_h, b_l[sub], b_l[sub + 2]);
                    mma_bf16(acc[mt][nt], a_l, b_h[sub], b_h[sub + 2]);
                }
            }
        }
        __syncthreads();
    }

    // ---- epilogue
    int g = l >> 2, tg = l & 3;
#pragma unroll
    for (int mt = 0; mt < 2; mt++) {
        int row0 = bm + wm * 32 + mt * 16 + g;
#pragma unroll
        for (int nt = 0; nt < 4; nt++) {
            int col = bn + wn * 32 + nt * 8 + tg * 2;
            float bx = 0.f, by = 0.f;
            if (BIAS) {
                float2 bv = *(const float2*)&bias[col];
                bx = bv.x; by = bv.y;
            }
            float2 o0 = make_float2(acc[mt][nt][0] + bx, acc[mt][nt][1] + by);
            float2 o1 = make_float2(acc[mt][nt][2] + bx, acc[mt][nt][3] + by);
            if (RELU) {
                o0.x = fmaxf(o0.x, 0.f); o0.y = fmaxf(o0.y, 0.f);
                o1.x = fmaxf(o1.x, 0.f); o1.y = fmaxf(o1.y, 0.f);
            }
            if (SPLIT) {
                uint32_t lp;
                if (row0 < M) {
                    uint32_t hp = split_pack_hi(o0.x, o0.y, lp);
                    *(uint32_t*)&Ch[(size_t)row0 * NTOT + col] = hp;
                    *(uint32_t*)&Cl[(size_t)row0 * NTOT + col] = lp;
                }
                if (row0 + 8 < M) {
                    uint32_t hp = split_pack_hi(o1.x, o1.y, lp);
                    *(uint32_t*)&Ch[(size_t)(row0 + 8) * NTOT + col] = hp;
                    *(uint32_t*)&Cl[(size_t)(row0 + 8) * NTOT + col] = lp;
                }
            } else {
                if (row0 < M)
                    *(float2*)&Cf[(size_t)row0 * NTOT + col] = o0;
                if (row0 + 8 < M)
                    *(float2*)&Cf[(size_t)(row0 + 8) * NTOT + col] = o1;
            }
        }
    }
}

// -------- init aggregation: agg[i] = h[i]/deg[i] (+ b); opt. store dinv ----
template<int C, bool BIAS, bool WDINV>
__global__ void k_init_agg(const float* __restrict__ h,
                           const float* __restrict__ bias,
                           float* __restrict__ agg)
{
    const int V = C / 4;
    int idx = blockIdx.x * 256 + threadIdx.x;
    if (idx >= NN * V) return;
    int node = idx / V;
    int v    = idx % V;
    float di;
    if (WDINV) {
        di = rsqrtf(g_deg[node]);
        if (v == 0) g_dinv[node] = di;
    } else {
        di = g_dinv[node];
    }
    float s = di * di;
    float4 hv = ((const float4*)h)[(size_t)node * V + v];
    float4 o;
    if (BIAS) {
        float4 bv = ((const float4*)bias)[v];
        o.x = fmaf(hv.x, s, bv.x);
        o.y = fmaf(hv.y, s, bv.y);
        o.z = fmaf(hv.z, s, bv.z);
        o.w = fmaf(hv.w, s, bv.w);
    } else {
        o.x = hv.x * s; o.y = hv.y * s; o.z = hv.z * s; o.w = hv.w * s;
    }
    ((float4*)agg)[(size_t)node * V + v] = o;
}

// ---------------- edge scatter: agg[dst] += h[src] * dinv[src]*dinv[dst] ---
template<int C, int LPE>
__global__ void k_scatter(const int* __restrict__ src, const int* __restrict__ dst,
                          const float* __restrict__ h, float* __restrict__ agg)
{
    const int V = C / 4;
    int t   = blockIdx.x * 256 + threadIdx.x;
    int e   = t / LPE;
    int sub = t % LPE;
    if (e >= ECNT) return;
    int s = src[e];
    int d = dst[e];
    float norm = g_dinv[s] * g_dinv[d];
    const float4* hp = (const float4*)h   + (size_t)s * V;
    float4*       ap = (float4*)agg       + (size_t)d * V;
#pragma unroll
    for (int v = sub; v < V; v += LPE) {
        float4 hv = hp[v];
        float mx = hv.x * norm, my = hv.y * norm, mz = hv.z * norm, mw = hv.w * norm;
        asm volatile("red.global.add.v4.f32 [%0], {%1, %2, %3, %4};"
                     :: "l"(ap + v), "f"(mx), "f"(my), "f"(mz), "f"(mw)
                     : "memory");
    }
}

// ---------------- launch ---------------------------------------------------
extern "C" void kernel_launch(void* const* d_in, const int* in_sizes, int n_in,
                              void* d_out, int out_size)
{
    const float* x   = (const float*)d_in[0];
    const int*   ei  = (const int*)  d_in[1];
    const float* W1  = (const float*)d_in[2];
    const float* b1  = (const float*)d_in[3];
    const float* W2  = (const float*)d_in[4];
    const float* b2  = (const float*)d_in[5];
    const float* Wd1 = (const float*)d_in[6];
    const float* bd1 = (const float*)d_in[7];
    const float* Wd2 = (const float*)d_in[8];
    const float* bd2 = (const float*)d_in[9];
    float* out = (float*)d_out;

    const int* srcp = ei;
    const int* dstp = ei + ECNT;

    float *p_aggx, *p_h2, *p_z;
    cudaGetSymbolAddress((void**)&p_aggx, g_aggx);
    cudaGetSymbolAddress((void**)&p_h2,   g_h2);
    cudaGetSymbolAddress((void**)&p_z,    g_z);
    __nv_bfloat16 *p_axh, *p_axl, *p_h1h, *p_h1l, *p_zh, *p_zl, *p_dh, *p_dl;
    __nv_bfloat16 *p_w1h, *p_w1l, *p_w2h, *p_w2l, *p_wd1h, *p_wd1l, *p_wd2h, *p_wd2l;
    cudaGetSymbolAddress((void**)&p_axh, g_axh);
    cudaGetSymbolAddress((void**)&p_axl, g_axl);
    cudaGetSymbolAddress((void**)&p_h1h, g_h1h);
    cudaGetSymbolAddress((void**)&p_h1l, g_h1l);
    cudaGetSymbolAddress((void**)&p_zh,  g_zh);
    cudaGetSymbolAddress((void**)&p_zl,  g_zl);
    cudaGetSymbolAddress((void**)&p_dh,  g_dh);
    cudaGetSymbolAddress((void**)&p_dl,  g_dl);
    cudaGetSymbolAddress((void**)&p_w1h, g_w1h);
    cudaGetSymbolAddress((void**)&p_w1l, g_w1l);
    cudaGetSymbolAddress((void**)&p_w2h, g_w2h);
    cudaGetSymbolAddress((void**)&p_w2l, g_w2l);
    cudaGetSymbolAddress((void**)&p_wd1h, g_wd1h);
    cudaGetSymbolAddress((void**)&p_wd1l, g_wd1l);
    cudaGetSymbolAddress((void**)&p_wd2h, g_wd2h);
    cudaGetSymbolAddress((void**)&p_wd2l, g_wd2l);

    const int STG = 2 * (128 * 72 * 2) + 2 * (64 * 72 * 2);  // 55296
    cudaFuncSetAttribute((const void*)k_gemm_bf<128, 256, true,  true,  true >,
                         cudaFuncAttributeMaxDynamicSharedMemorySize, 2 * STG);
    cudaFuncSetAttribute((const void*)k_gemm_bf<256, 64,  false, false, false>,
                         cudaFuncAttributeMaxDynamicSharedMemorySize, 2 * STG);
    cudaFuncSetAttribute((const void*)k_gemm_bf<64,  256, true,  true,  true >,
                         cudaFuncAttributeMaxDynamicSharedMemorySize, STG);
    cudaFuncSetAttribute((const void*)k_gemm_bf<256, 128, true,  false, false>,
                         cudaFuncAttributeMaxDynamicSharedMemorySize, 2 * STG);

    // --- prep (weight splits + deg init) + degree count
    k_prep<<<(98304 + NN + 255) / 256, 256>>>(W1, W2, Wd1, Wd2);
    k_deg_count<<<(ECNT + 255) / 256, 256>>>(dstp);

    const int MB = (NN + 127) / 128;   // 391 row-blocks

    // --- layer 1: aggx = Dsym-scatter(x); split; h1 = relu(aggx@W1+b1)
    k_init_agg<128,false,true><<<(NN * 32 + 255) / 256, 256>>>(x, nullptr, p_aggx);
    k_scatter<128,32><<<(ECNT * 32) / 256, 256>>>(srcp, dstp, x, p_aggx);
    k_split<<<(NN * 32 + 255) / 256, 256>>>(p_aggx, p_axh, p_axl, NN * 32);
    k_gemm_bf<128, 256, true, true, true><<<dim3(4, MB), 256, 2 * STG>>>(
        p_axh, p_axl, p_w1h, p_w1l, b1, nullptr, p_h1h, p_h1l);

    // --- layer 2: h2 = h1 @ W2 [fp32]; z = scatter(h2) + b2; split
    k_gemm_bf<256, 64, false, false, false><<<dim3(1, MB), 256, 2 * STG>>>(
        p_h1h, p_h1l, p_w2h, p_w2l, nullptr, p_h2, nullptr, nullptr);
    k_init_agg<64,true,false><<<(NN * 16 + 255) / 256, 256>>>(p_h2, b2, p_z);
    k_scatter<64,16><<<(ECNT * 16) / 256, 256>>>(srcp, dstp, p_h2, p_z);
    k_split<<<(NN * 16 + 255) / 256, 256>>>(p_z, p_zh, p_zl, NN * 16);

    // --- decoder: d = relu(z @ Wd1 + bd1); out = d @ Wd2 + bd2
    k_gemm_bf<64, 256, true, true, true><<<dim3(4, MB), 256, STG>>>(
        p_zh, p_zl, p_wd1h, p_wd1l, bd1, nullptr, p_dh, p_dl);
    k_gemm_bf<256, 128, true, false, false><<<dim3(2, MB), 256, 2 * STG>>>(
        p_dh, p_dl, p_wd2h, p_wd2l, bd2, out, nullptr, nullptr);
}